// round 3
// baseline (speedup 1.0000x reference)
#include <cuda_runtime.h>

// Problem constants
#define Bb 4
#define Hh 16
#define Ss 2048
#define Dd 64
#define BH 64               // Bb*Hh
#define TM 128              // query rows per CTA
#define TN 128              // key cols per tile
#define INV_TEMP 0.125f     // 1/8

// SMEM layout (floats). All float4 accesses 16B-aligned.
#define QS_STRIDE 68
#define VS_STRIDE 68
#define P_STRIDE  132
#define QS_OFF 0
#define KT_OFF (TM * QS_STRIDE)                 // 8704
#define KT_SIZE (Dd * 128)                      // 8192 (swizzled, no pad)
#define P_OFF  0                                 // overlays Qs+KT in phase 2
#define P_SIZE (TM * P_STRIDE)                  // 16896 = 8704+8192 exactly
#define VS_OFF (KT_OFF + KT_SIZE)               // 16896
#define MS_OFF (VS_OFF + TN * VS_STRIDE)        // 16896 + 8704 = 25600
#define LS_OFF (MS_OFF + TM)                    // 25728
#define SMEM_FLOATS (LS_OFF + TM)               // 25856 -> 103424 bytes

// KT xor-swizzle: logical (dim row, key col) -> physical float index
#define KT_SWZ(row, col) \
    (((row) << 7) + (((((col) >> 2) ^ (((row) >> 2) & 7)) << 2) | ((col) & 3)))

__global__ __launch_bounds__(256)
void sdpa_fused_kernel(const float* __restrict__ q,
                       const float* __restrict__ k,
                       const float* __restrict__ v,
                       float* __restrict__ out)
{
    extern __shared__ float sm[];
    const int qt  = blockIdx.x;          // 0..15  query tile
    const int bh  = blockIdx.y;          // 0..63  (b*H + h)
    const int tid = threadIdx.x;         // 0..255
    const int ty  = tid >> 4;            // 0..15 -> rows ty*8 .. ty*8+7
    const int tx  = tid & 15;            // 0..15
    const int q0  = qt * TM;

    const float* qbase = q + (size_t)bh * Ss * Dd + (size_t)q0 * Dd;
    const float* kbase = k + (size_t)bh * Ss * Dd;
    const float* vbase = v + (size_t)bh * Ss * Dd;
    float* obase = out + (size_t)bh * Ss * Dd + (size_t)q0 * Dd;
    float* attn  = out + (size_t)BH * Ss * Dd          // start of attn region
                       + (size_t)bh * Ss * Ss + (size_t)q0 * Ss;

    float* Qs = sm + QS_OFF;   // [TM][QS_STRIDE]
    float* KT = sm + KT_OFF;   // swizzled [Dd][128]
    float* P  = sm + P_OFF;    // [TM][P_STRIDE]  (phase 2, overlays Qs/KT)
    float* Vs = sm + VS_OFF;   // [TN][VS_STRIDE]
    float* mS = sm + MS_OFF;   // [TM] row max
    float* lS = sm + LS_OFF;   // [TM] row sum (then inverted)

    if (tid < TM) { mS[tid] = -1e30f; lS[tid] = 0.0f; }

    // Load Q tile (scaled by 1/temperature), row-major with pad
    #pragma unroll
    for (int it = 0; it < 8; it++) {
        int e = (it * 256 + tid) * 4;
        int r = e >> 6, d = e & 63;
        float4 qv = *(const float4*)(qbase + (size_t)r * Dd + d);
        qv.x *= INV_TEMP; qv.y *= INV_TEMP; qv.z *= INV_TEMP; qv.w *= INV_TEMP;
        *(float4*)(Qs + r * QS_STRIDE + d) = qv;
    }
    __syncthreads();

    // =================== Phase 1: raw scores + online (m, l) ===================
    for (int t = 0; t < Ss / TN; t++) {
        const int c0 = t * TN;
        // Load K tile transposed into swizzled KT[dim][key]
        #pragma unroll
        for (int it = 0; it < 8; it++) {
            int e = (it * 256 + tid) * 4;
            int c = e >> 6, d = e & 63;    // c = key row, d = dim base (mult of 4)
            float4 kv = *(const float4*)(kbase + (size_t)(c0 + c) * Dd + d);
            KT[KT_SWZ(d + 0, c)] = kv.x;
            KT[KT_SWZ(d + 1, c)] = kv.y;
            KT[KT_SWZ(d + 2, c)] = kv.z;
            KT[KT_SWZ(d + 3, c)] = kv.w;
        }
        __syncthreads();

        // 128x128 score tile: thread computes rows ty*8+i, cols {tx*4+j, 64+tx*4+j}
        float acc[8][8];
        #pragma unroll
        for (int i = 0; i < 8; i++)
            #pragma unroll
            for (int j = 0; j < 8; j++) acc[i][j] = 0.0f;

        #pragma unroll 4
        for (int d = 0; d < Dd; d++) {
            float qv[8];
            #pragma unroll
            for (int i = 0; i < 8; i++)
                qv[i] = Qs[(ty * 8 + i) * QS_STRIDE + d];   // broadcast across tx
            const int s = (d >> 2) & 7;
            // logical key-group tx -> physical group tx^s (aligned float4)
            float4 k0 = *(float4*)(KT + (d << 7) + ((tx ^ s) << 2));
            float4 k1 = *(float4*)(KT + (d << 7) + (((16 + tx) ^ s) << 2));
            #pragma unroll
            for (int i = 0; i < 8; i++) {
                acc[i][0] += qv[i] * k0.x;  acc[i][1] += qv[i] * k0.y;
                acc[i][2] += qv[i] * k0.z;  acc[i][3] += qv[i] * k0.w;
                acc[i][4] += qv[i] * k1.x;  acc[i][5] += qv[i] * k1.y;
                acc[i][6] += qv[i] * k1.z;  acc[i][7] += qv[i] * k1.w;
            }
        }

        // Per-row online stats (16 lanes share a row) + write raw scores to gmem
        #pragma unroll
        for (int i = 0; i < 8; i++) {
            const int r = ty * 8 + i;
            float mx = acc[i][0];
            #pragma unroll
            for (int j = 1; j < 8; j++) mx = fmaxf(mx, acc[i][j]);
            #pragma unroll
            for (int o = 8; o >= 1; o >>= 1)
                mx = fmaxf(mx, __shfl_xor_sync(0xffffffffu, mx, o));
            const float mold = mS[r];
            const float mnew = fmaxf(mold, mx);
            float ps = 0.0f;
            #pragma unroll
            for (int j = 0; j < 8; j++) ps += __expf(acc[i][j] - mnew);
            #pragma unroll
            for (int o = 8; o >= 1; o >>= 1)
                ps += __shfl_xor_sync(0xffffffffu, ps, o);
            if (tx == 0) {
                lS[r] = lS[r] * __expf(mold - mnew) + ps;
                mS[r] = mnew;
            }
            float4 s0 = make_float4(acc[i][0], acc[i][1], acc[i][2], acc[i][3]);
            float4 s1 = make_float4(acc[i][4], acc[i][5], acc[i][6], acc[i][7]);
            *(float4*)(attn + (size_t)r * Ss + c0 + tx * 4)      = s0;
            *(float4*)(attn + (size_t)r * Ss + c0 + 64 + tx * 4) = s1;
        }
        __syncthreads();
    }

    // Invert l once
    if (tid < TM) lS[tid] = 1.0f / lS[tid];
    __syncthreads();

    // =================== Phase 2: p = exp(s-m)/l, write attn, O += P*V ===================
    float oacc[8][4];
    #pragma unroll
    for (int i = 0; i < 8; i++)
        #pragma unroll
        for (int j = 0; j < 4; j++) oacc[i][j] = 0.0f;

    for (int t = 0; t < Ss / TN; t++) {
        const int c0 = t * TN;
        // V tile: [kk][d]
        #pragma unroll
        for (int it = 0; it < 8; it++) {
            int e = (it * 256 + tid) * 4;
            int kk = e >> 6, d = e & 63;
            *(float4*)(Vs + kk * VS_STRIDE + d) =
                *(const float4*)(vbase + (size_t)(c0 + kk) * Dd + d);
        }
        // Score tile: gmem -> exp-normalize -> gmem (final attn) + SMEM P
        #pragma unroll
        for (int it = 0; it < 16; it++) {
            int e = (it * 256 + tid) * 4;
            int r = e >> 7, col = e & 127;            // each warp: one full 128-col row
            size_t ga = (size_t)r * Ss + c0 + col;
            float4 s4 = *(float4*)(attn + ga);
            const float mr = mS[r];
            const float il = lS[r];
            s4.x = __expf(s4.x - mr) * il;
            s4.y = __expf(s4.y - mr) * il;
            s4.z = __expf(s4.z - mr) * il;
            s4.w = __expf(s4.w - mr) * il;
            *(float4*)(attn + ga) = s4;
            *(float4*)(P + r * P_STRIDE + col) = s4;
        }
        __syncthreads();

        // O[r][c] += P[r][kk] * V[kk][c] ; thread: rows ty*8+i, cols tx*4+j
        #pragma unroll 4
        for (int kk = 0; kk < TN; kk++) {
            float pv[8];
            #pragma unroll
            for (int i = 0; i < 8; i++)
                pv[i] = P[(ty * 8 + i) * P_STRIDE + kk];   // broadcast across tx
            float4 vv = *(float4*)(Vs + kk * VS_STRIDE + tx * 4);
            #pragma unroll
            for (int i = 0; i < 8; i++) {
                oacc[i][0] += pv[i] * vv.x;
                oacc[i][1] += pv[i] * vv.y;
                oacc[i][2] += pv[i] * vv.z;
                oacc[i][3] += pv[i] * vv.w;
            }
        }
        __syncthreads();
    }

    // Write output tile [TM][Dd]
    #pragma unroll
    for (int i = 0; i < 8; i++) {
        const int r = ty * 8 + i;
        float4 o = make_float4(oacc[i][0], oacc[i][1], oacc[i][2], oacc[i][3]);
        *(float4*)(obase + (size_t)r * Dd + tx * 4) = o;
    }
}

extern "C" void kernel_launch(void* const* d_in, const int* in_sizes, int n_in,
                              void* d_out, int out_size)
{
    const float* q = (const float*)d_in[0];
    const float* k = (const float*)d_in[1];
    const float* v = (const float*)d_in[2];
    float* out = (float*)d_out;

    const size_t smem_bytes = (size_t)SMEM_FLOATS * sizeof(float);  // 103424
    cudaFuncSetAttribute(sdpa_fused_kernel,
                         cudaFuncAttributeMaxDynamicSharedMemorySize,
                         (int)smem_bytes);

    dim3 grid(Ss / TM, BH);   // (16, 64) = 1024 CTAs
    dim3 block(256);
    sdpa_fused_kernel<<<grid, block, smem_bytes>>>(q, k, v, out);
}

// round 8
// speedup vs baseline: 2.8753x; 2.8753x over previous
#include <cuda_runtime.h>
#include <cuda_bf16.h>
#include <cstdint>

#define Ss 2048
#define Dd 64
#define BH 64
#define TM 128
#define TN 128
#define INV_TEMP 0.125f

// SMEM layout (bytes): bf16 tiles, 128 rows x 64 cols -> 128B/row, 16KB each
#define OFF_Q   0
#define OFF_QL  16384
#define OFF_K   32768
#define OFF_KL  49152
#define OFF_V   65536
#define OFF_VL  81920
#define OFF_LS  98304   // 128 floats: row sums -> then 1/l
#define SMEM_BYTES (98304 + 512)

__device__ __forceinline__ uint32_t smem_u32(const void* p) {
    uint32_t a;
    asm("{ .reg .u64 t; cvta.to.shared.u64 t, %1; cvt.u32.u64 %0, t; }" : "=r"(a) : "l"(p));
    return a;
}
// byte offset in a [128][64] bf16 tile; 16B chunks xor-swizzled by row
__device__ __forceinline__ uint32_t swz(int row, int dim) {
    return (uint32_t)((row << 7) + ((((dim >> 3) ^ (row & 7)) << 4)) + ((dim & 7) << 1));
}
// pack two f32 -> bf16x2 (e0 = low half, e1 = high half)
__device__ __forceinline__ uint32_t pack2(float e0, float e1) {
    uint32_t r;
    asm("cvt.rn.bf16x2.f32 %0, %1, %2;" : "=r"(r) : "f"(e1), "f"(e0));
    return r;
}
__device__ __forceinline__ void ldsm4(uint32_t addr, uint32_t* r) {
    asm volatile("ldmatrix.sync.aligned.m8n8.x4.shared.b16 {%0,%1,%2,%3}, [%4];"
        : "=r"(r[0]), "=r"(r[1]), "=r"(r[2]), "=r"(r[3]) : "r"(addr));
}
__device__ __forceinline__ void ldsm4t(uint32_t addr, uint32_t* r) {
    asm volatile("ldmatrix.sync.aligned.m8n8.x4.trans.shared.b16 {%0,%1,%2,%3}, [%4];"
        : "=r"(r[0]), "=r"(r[1]), "=r"(r[2]), "=r"(r[3]) : "r"(addr));
}
__device__ __forceinline__ void mma_bf16(float* c, const uint32_t* a, uint32_t b0, uint32_t b1) {
    asm volatile("mma.sync.aligned.m16n8k16.row.col.f32.bf16.bf16.f32 "
        "{%0,%1,%2,%3}, {%4,%5,%6,%7}, {%8,%9}, {%0,%1,%2,%3};"
        : "+f"(c[0]), "+f"(c[1]), "+f"(c[2]), "+f"(c[3])
        : "r"(a[0]), "r"(a[1]), "r"(a[2]), "r"(a[3]), "r"(b0), "r"(b1));
}

// stage a [128][64] fp32 gmem tile -> bf16 hi/lo swizzled SMEM tiles
__device__ __forceinline__ void stage_tile(const float* __restrict__ g,
                                           char* smhi, char* smlo, int tid, float scale) {
    #pragma unroll
    for (int it = 0; it < 8; it++) {
        int i = it * 256 + tid;
        int r = i >> 4, d = (i & 15) << 2;
        float4 x = *(const float4*)(g + (size_t)r * Dd + d);
        x.x *= scale; x.y *= scale; x.z *= scale; x.w *= scale;
        float h0 = __bfloat162float(__float2bfloat16(x.x));
        float h1 = __bfloat162float(__float2bfloat16(x.y));
        float h2 = __bfloat162float(__float2bfloat16(x.z));
        float h3 = __bfloat162float(__float2bfloat16(x.w));
        uint2 hh = make_uint2(pack2(h0, h1), pack2(h2, h3));
        uint2 ll = make_uint2(pack2(x.x - h0, x.y - h1), pack2(x.z - h2, x.w - h3));
        uint32_t o = swz(r, d);
        *(uint2*)(smhi + o) = hh;
        *(uint2*)(smlo + o) = ll;
    }
}

// S = Q.K^T for one pair of 8-col ntiles (keys kc*16..+15), K=64, 3-product split
__device__ __forceinline__ void compute_S_pair(
    uint32_t sbK, uint32_t sbKL, int kc, int lane,
    const uint32_t (&qh)[4][4], const uint32_t (&ql)[4][4], float (&c)[2][4])
{
    #pragma unroll
    for (int u = 0; u < 2; u++)
        #pragma unroll
        for (int j = 0; j < 4; j++) c[u][j] = 0.0f;
    const int key  = kc * 16 + ((lane >> 4) << 3) + (lane & 7);
    const int dimo = ((lane >> 3) & 1) << 3;
    #pragma unroll
    for (int ks = 0; ks < 4; ks++) {
        uint32_t off = swz(key, ks * 16 + dimo);
        uint32_t kh[4], kl[4];
        ldsm4(sbK + off, kh);
        ldsm4(sbKL + off, kl);
        mma_bf16(c[0], qh[ks], kh[0], kh[1]);
        mma_bf16(c[0], qh[ks], kl[0], kl[1]);
        mma_bf16(c[0], ql[ks], kh[0], kh[1]);
        mma_bf16(c[1], qh[ks], kh[2], kh[3]);
        mma_bf16(c[1], qh[ks], kl[2], kl[3]);
        mma_bf16(c[1], ql[ks], kh[2], kh[3]);
    }
}

__global__ __launch_bounds__(256)
void sdpa_mma_kernel(const float* __restrict__ q,
                     const float* __restrict__ k,
                     const float* __restrict__ v,
                     float* __restrict__ out)
{
    extern __shared__ char sm[];
    const uint32_t sb = smem_u32(sm);
    const int tid  = threadIdx.x;
    const int wid  = tid >> 5;
    const int lane = tid & 31;
    const int qt = blockIdx.x, bh = blockIdx.y;
    const int q0 = qt * TM;
    const int rowb = wid * 16;              // warp's first q-row in tile

    const float* qbase = q + (size_t)bh * Ss * Dd + (size_t)q0 * Dd;
    const float* kbase = k + (size_t)bh * Ss * Dd;
    const float* vbase = v + (size_t)bh * Ss * Dd;
    float* obase = out + (size_t)bh * Ss * Dd + (size_t)q0 * Dd;
    float* attn  = out + (size_t)BH * Ss * Dd + (size_t)bh * Ss * Ss + (size_t)q0 * Ss;
    float* lsS = (float*)(sm + OFF_LS);

    // ---------- stage Q (scaled), preload Q a-fragments ----------
    stage_tile(qbase, sm + OFF_Q, sm + OFF_QL, tid, INV_TEMP);
    __syncthreads();

    uint32_t qh[4][4], ql[4][4];
    {
        const int row = rowb + (((lane >> 3) & 1) << 3) + (lane & 7);
        const int dmo = (lane >> 4) << 3;
        #pragma unroll
        for (int ks = 0; ks < 4; ks++) {
            uint32_t off = swz(row, ks * 16 + dmo);
            ldsm4(sb + OFF_Q  + off, qh[ks]);
            ldsm4(sb + OFF_QL + off, ql[ks]);
        }
    }

    // ================= pass A: row sums of exp(S) =================
    float ls0 = 0.0f, ls1 = 0.0f;
    for (int t = 0; t < Ss / TN; t++) {
        __syncthreads();
        stage_tile(kbase + (size_t)t * TN * Dd, sm + OFF_K, sm + OFF_KL, tid, 1.0f);
        __syncthreads();
        #pragma unroll
        for (int kc = 0; kc < 8; kc++) {
            float c[2][4];
            compute_S_pair(sb + OFF_K, sb + OFF_KL, kc, lane, qh, ql, c);
            #pragma unroll
            for (int u = 0; u < 2; u++) {
                ls0 += __expf(c[u][0]) + __expf(c[u][1]);
                ls1 += __expf(c[u][2]) + __expf(c[u][3]);
            }
        }
    }
    // reduce across the 4 lanes sharing each row
    ls0 += __shfl_xor_sync(0xffffffffu, ls0, 1);
    ls0 += __shfl_xor_sync(0xffffffffu, ls0, 2);
    ls1 += __shfl_xor_sync(0xffffffffu, ls1, 1);
    ls1 += __shfl_xor_sync(0xffffffffu, ls1, 2);
    if ((lane & 3) == 0) {
        lsS[rowb + (lane >> 2)]     = ls0;
        lsS[rowb + (lane >> 2) + 8] = ls1;
    }
    __syncthreads();
    if (tid < TM) lsS[tid] = 1.0f / lsS[tid];
    __syncthreads();
    const float inv0 = lsS[rowb + (lane >> 2)];
    const float inv1 = lsS[rowb + (lane >> 2) + 8];

    // ================= pass B: attn = exp(S)/l, O = attn.V =================
    float oacc[8][4];
    #pragma unroll
    for (int n = 0; n < 8; n++)
        #pragma unroll
        for (int j = 0; j < 4; j++) oacc[n][j] = 0.0f;

    const int r0 = rowb + (lane >> 2);       // c-frag row (lo)
    const int cB = 2 * (lane & 3);           // c-frag col pair base

    for (int t = 0; t < Ss / TN; t++) {
        __syncthreads();
        stage_tile(kbase + (size_t)t * TN * Dd, sm + OFF_K, sm + OFF_KL, tid, 1.0f);
        stage_tile(vbase + (size_t)t * TN * Dd, sm + OFF_V, sm + OFF_VL, tid, 1.0f);
        __syncthreads();

        #pragma unroll
        for (int kc = 0; kc < 8; kc++) {
            float c[2][4];
            compute_S_pair(sb + OFF_K, sb + OFF_KL, kc, lane, qh, ql, c);

            // normalized probabilities
            float pe[2][4];
            #pragma unroll
            for (int u = 0; u < 2; u++) {
                pe[u][0] = __expf(c[u][0]) * inv0;
                pe[u][1] = __expf(c[u][1]) * inv0;
                pe[u][2] = __expf(c[u][2]) * inv1;
                pe[u][3] = __expf(c[u][3]) * inv1;
            }
            // write attn (final values, written exactly once)
            {
                const int col = t * TN + kc * 16 + cB;
                *(float2*)(attn + (size_t)r0 * Ss + col)           = make_float2(pe[0][0], pe[0][1]);
                *(float2*)(attn + (size_t)(r0 + 8) * Ss + col)     = make_float2(pe[0][2], pe[0][3]);
                *(float2*)(attn + (size_t)r0 * Ss + col + 8)       = make_float2(pe[1][0], pe[1][1]);
                *(float2*)(attn + (size_t)(r0 + 8) * Ss + col + 8) = make_float2(pe[1][2], pe[1][3]);
            }
            // convert to P a-fragments (hi/lo split), C->A layout identity
            uint32_t ah[4], al[4];
            #pragma unroll
            for (int u = 0; u < 2; u++) {
                float h0 = __bfloat162float(__float2bfloat16(pe[u][0]));
                float h1 = __bfloat162float(__float2bfloat16(pe[u][1]));
                float h2 = __bfloat162float(__float2bfloat16(pe[u][2]));
                float h3 = __bfloat162float(__float2bfloat16(pe[u][3]));
                ah[2 * u + 0] = pack2(h0, h1);
                ah[2 * u + 1] = pack2(h2, h3);
                al[2 * u + 0] = pack2(pe[u][0] - h0, pe[u][1] - h1);
                al[2 * u + 1] = pack2(pe[u][2] - h2, pe[u][3] - h3);
            }
            // wait: a-frag order must be (rows lo k-lo, rows hi k-lo, rows lo k-hi, rows hi k-hi)
            // ah currently: [nt0 lo, nt0 hi, nt1 lo, nt1 hi] == (a0,a1,a2,a3) — correct.

            // O += P.V for this 16-key chunk
            const int vkey = kc * 16 + (((lane >> 3) & 1) << 3) + (lane & 7);
            const int vdmo = (lane >> 4) << 3;
            #pragma unroll
            for (int p = 0; p < 4; p++) {
                uint32_t off = swz(vkey, p * 16 + vdmo);
                uint32_t vh[4], vl[4];
                ldsm4t(sb + OFF_V  + off, vh);
                ldsm4t(sb + OFF_VL + off, vl);
                mma_bf16(oacc[2 * p],     ah, vh[0], vh[1]);
                mma_bf16(oacc[2 * p],     ah, vl[0], vl[1]);
                mma_bf16(oacc[2 * p],     al, vh[0], vh[1]);
                mma_bf16(oacc[2 * p + 1], ah, vh[2], vh[3]);
                mma_bf16(oacc[2 * p + 1], ah, vl[2], vl[3]);
                mma_bf16(oacc[2 * p + 1], al, vh[2], vh[3]);
            }
        }
    }

    // ---------- write O ----------
    #pragma unroll
    for (int n = 0; n < 8; n++) {
        const int col = 8 * n + cB;
        *(float2*)(obase + (size_t)r0 * Dd + col)       = make_float2(oacc[n][0], oacc[n][1]);
        *(float2*)(obase + (size_t)(r0 + 8) * Dd + col) = make_float2(oacc[n][2], oacc[n][3]);
    }
}

extern "C" void kernel_launch(void* const* d_in, const int* in_sizes, int n_in,
                              void* d_out, int out_size)
{
    const float* q = (const float*)d_in[0];
    const float* k = (const float*)d_in[1];
    const float* v = (const float*)d_in[2];
    float* out = (float*)d_out;

    cudaFuncSetAttribute(sdpa_mma_kernel,
                         cudaFuncAttributeMaxDynamicSharedMemorySize, SMEM_BYTES);
    dim3 grid(Ss / TM, BH);   // (16, 64)
    sdpa_mma_kernel<<<grid, 256, SMEM_BYTES>>>(q, k, v, out);
}